// round 16
// baseline (speedup 1.0000x reference)
#include <cuda_runtime.h>
#include <cuda_bf16.h>
#include <cstdint>
#include <math.h>

#define BB 32
#define TT 2048
#define FF 64
#define HH 256
#define GG 768
#define MTOT (BB*TT)

typedef unsigned long long u64;

// scratch (static device arrays: the sanctioned no-alloc workaround)
__device__ float g_xb[(size_t)MTOT*GG];                 // projection buffer (fp32)
__device__ __nv_bfloat16 g_xnh[(size_t)MTOT*FF];        // LN out hi
__device__ __nv_bfloat16 g_xnl[(size_t)MTOT*FF];        // LN out lo
__device__ __nv_bfloat16 g_h1h[(size_t)MTOT*HH];        // GRU1 seq hi
__device__ __nv_bfloat16 g_h1l[(size_t)MTOT*HH];        // GRU1 seq lo
__device__ __nv_bfloat16 g_wh[GG*HH];                   // packed W [N][K] hi
__device__ __nv_bfloat16 g_wl[GG*HH];                   // packed W [N][K] lo
__device__ float g_h2[BB*HH];

__device__ __forceinline__ u64 ffma2(u64 a, u64 b, u64 c) {
    u64 d;
    asm("fma.rn.f32x2 %0, %1, %2, %3;" : "=l"(d) : "l"(a), "l"(b), "l"(c));
    return d;
}
__device__ __forceinline__ u64 addf2(u64 a, u64 b) {
    u64 d;
    asm("add.rn.f32x2 %0, %1, %2;" : "=l"(d) : "l"(a), "l"(b));
    return d;
}
__device__ __forceinline__ u64 pack2(float x, float y) {
    u64 d;
    asm("mov.b64 %0, {%1, %2};" : "=l"(d) : "f"(x), "f"(y));
    return d;
}
__device__ __forceinline__ void unpack2(u64 v, float& lo, float& hi) {
    asm("mov.b64 {%0, %1}, %2;" : "=f"(lo), "=f"(hi) : "l"(v));
}
__device__ __forceinline__ uint32_t smem_u32(const void* p) {
    return (uint32_t)__cvta_generic_to_shared(p);
}

#define MBAR_INIT(addr, cnt) \
    asm volatile("mbarrier.init.shared.b64 [%0], %1;" :: "r"(addr), "r"(cnt) : "memory")
#define MBAR_EXPECT_TX(addr, bytes) \
    asm volatile("mbarrier.arrive.expect_tx.shared.b64 _, [%0], %1;" :: "r"(addr), "r"(bytes) : "memory")
#define MBAR_WAIT_PARITY(addr, par) do { \
    uint32_t _done = 0; \
    while (!_done) { \
        asm volatile("{\n\t.reg .pred P;\n\t" \
            "mbarrier.try_wait.parity.acquire.cta.shared::cta.b64 P, [%1], %2, 0x989680;\n\t" \
            "selp.b32 %0, 1, 0, P;\n\t}" \
            : "=r"(_done) : "r"(addr), "r"(par) : "memory"); \
    } } while (0)
#define ST_ASYNC_F32(raddr, val, rbar) \
    asm volatile("st.async.shared::cluster.mbarrier::complete_tx::bytes.b32 [%0], %1, [%2];" \
        :: "r"(raddr), "r"(val), "r"(rbar) : "memory")
#define BAR_ARRIVE(id, n) \
    asm volatile("bar.arrive %0, %1;" :: "r"(id), "r"(n) : "memory")
#define BAR_SYNC(id, n) \
    asm volatile("bar.sync %0, %1;" :: "r"(id), "r"(n) : "memory")

// mma.sync bf16: D(f32) += A(bf16) * B(bf16). m16n8k16, row.col.
#define MMA_BF16(c, a, b) \
    asm volatile("mma.sync.aligned.m16n8k16.row.col.f32.bf16.bf16.f32 " \
        "{%0,%1,%2,%3}, {%4,%5,%6,%7}, {%8,%9}, {%0,%1,%2,%3};" \
        : "+f"((c)[0]), "+f"((c)[1]), "+f"((c)[2]), "+f"((c)[3]) \
        : "r"((a)[0]), "r"((a)[1]), "r"((a)[2]), "r"((a)[3]), \
          "r"((b)[0]), "r"((b)[1]))

// ---------------- LayerNorm -> bf16 hi/lo split ----------------
__global__ void __launch_bounds__(256) ln_kernel(const float* __restrict__ x,
        const float* __restrict__ gamma, const float* __restrict__ beta,
        __nv_bfloat16* __restrict__ xnh, __nv_bfloat16* __restrict__ xnl)
{
    int row  = blockIdx.x * 8 + (threadIdx.x >> 5);
    int lane = threadIdx.x & 31;
    const float* xr = x + (size_t)row * FF;
    float v0 = xr[lane], v1 = xr[lane + 32];
    float s = v0 + v1;
    #pragma unroll
    for (int o = 16; o > 0; o >>= 1) s += __shfl_xor_sync(0xffffffffu, s, o);
    float mu = s * (1.f / FF);
    float d0 = v0 - mu, d1 = v1 - mu;
    float q = d0 * d0 + d1 * d1;
    #pragma unroll
    for (int o = 16; o > 0; o >>= 1) q += __shfl_xor_sync(0xffffffffu, q, o);
    float inv = rsqrtf(q * (1.f / FF) + 1e-3f);
    float o0 = d0 * inv * gamma[lane]      + beta[lane];
    float o1 = d1 * inv * gamma[lane + 32] + beta[lane + 32];
    size_t i0 = (size_t)row * FF + lane;
    __nv_bfloat16 h0 = __float2bfloat16(o0);
    __nv_bfloat16 h1 = __float2bfloat16(o1);
    xnh[i0] = h0;      xnl[i0]      = __float2bfloat16(o0 - __bfloat162float(h0));
    xnh[i0 + 32] = h1; xnl[i0 + 32] = __float2bfloat16(o1 - __bfloat162float(h1));
}

// ---- pack weights: W[K][N] fp32 -> [N][K] bf16 hi/lo ----
__global__ void wconv_kernel(const float* __restrict__ Wm,
        __nv_bfloat16* __restrict__ Wh, __nv_bfloat16* __restrict__ Wl, int K)
{
    int idx = blockIdx.x * 256 + threadIdx.x;
    if (idx >= K * GG) return;
    int n = idx / K, k = idx - n * K;
    float v = Wm[(size_t)k * GG + n];
    __nv_bfloat16 h = __float2bfloat16(v);
    Wh[idx] = h;
    Wl[idx] = __float2bfloat16(v - __bfloat162float(h));
}

// ---- mma.sync bf16 GEMM (unchanged from R15 pass) ----
__global__ void __launch_bounds__(256) gemm_mma(
        const __nv_bfloat16* __restrict__ Ah, const __nv_bfloat16* __restrict__ Al,
        const __nv_bfloat16* __restrict__ Bh, const __nv_bfloat16* __restrict__ Bl,
        const float* __restrict__ bias, float* __restrict__ C, int K)
{
    __shared__ __align__(16) __nv_bfloat16 sAh[128][40];
    __shared__ __align__(16) __nv_bfloat16 sAl[128][40];
    __shared__ __align__(16) __nv_bfloat16 sBh[128][40];
    __shared__ __align__(16) __nv_bfloat16 sBl[128][40];

    const int tid = threadIdx.x, wid = tid >> 5, lane = tid & 31;
    const int bm = blockIdx.y * 128, bn = blockIdx.x * 128;
    const int wm = wid & 1, wn = wid >> 1;
    const int g = lane >> 2, tig = lane & 3;

    float c[4][4][4];
    #pragma unroll
    for (int i = 0; i < 4; ++i)
        #pragma unroll
        for (int j = 0; j < 4; ++j)
            #pragma unroll
            for (int r = 0; r < 4; ++r) c[i][j][r] = 0.f;

    for (int k0 = 0; k0 < K; k0 += 32) {
        __syncthreads();
        #pragma unroll
        for (int i = tid; i < 512; i += 256) {
            int row = i >> 2, seg = i & 3;
            size_t offA = (size_t)(bm + row) * K + k0 + seg * 8;
            size_t offB = (size_t)(bn + row) * K + k0 + seg * 8;
            *(uint4*)&sAh[row][seg * 8] = *(const uint4*)(Ah + offA);
            *(uint4*)&sAl[row][seg * 8] = *(const uint4*)(Al + offA);
            *(uint4*)&sBh[row][seg * 8] = *(const uint4*)(Bh + offB);
            *(uint4*)&sBl[row][seg * 8] = *(const uint4*)(Bl + offB);
        }
        __syncthreads();
        #pragma unroll
        for (int kf = 0; kf < 2; ++kf) {
            const int kc = kf * 16 + tig * 2;
            uint32_t aH[4][4], aL[4][4], bH[4][2], bL[4][2];
            #pragma unroll
            for (int mf = 0; mf < 4; ++mf) {
                int r = wm * 64 + mf * 16 + g;
                aH[mf][0] = *(const uint32_t*)&sAh[r][kc];
                aH[mf][1] = *(const uint32_t*)&sAh[r + 8][kc];
                aH[mf][2] = *(const uint32_t*)&sAh[r][kc + 8];
                aH[mf][3] = *(const uint32_t*)&sAh[r + 8][kc + 8];
                aL[mf][0] = *(const uint32_t*)&sAl[r][kc];
                aL[mf][1] = *(const uint32_t*)&sAl[r + 8][kc];
                aL[mf][2] = *(const uint32_t*)&sAl[r][kc + 8];
                aL[mf][3] = *(const uint32_t*)&sAl[r + 8][kc + 8];
            }
            #pragma unroll
            for (int nf = 0; nf < 4; ++nf) {
                int n = wn * 32 + nf * 8 + g;
                bH[nf][0] = *(const uint32_t*)&sBh[n][kc];
                bH[nf][1] = *(const uint32_t*)&sBh[n][kc + 8];
                bL[nf][0] = *(const uint32_t*)&sBl[n][kc];
                bL[nf][1] = *(const uint32_t*)&sBl[n][kc + 8];
            }
            #pragma unroll
            for (int mf = 0; mf < 4; ++mf)
                #pragma unroll
                for (int nf = 0; nf < 4; ++nf) {
                    MMA_BF16(c[mf][nf], aH[mf], bH[nf]);
                    MMA_BF16(c[mf][nf], aH[mf], bL[nf]);
                    MMA_BF16(c[mf][nf], aL[mf], bH[nf]);
                }
        }
    }
    #pragma unroll
    for (int mf = 0; mf < 4; ++mf) {
        int r0 = bm + wm * 64 + mf * 16 + g;
        #pragma unroll
        for (int nf = 0; nf < 4; ++nf) {
            int col = bn + wn * 32 + nf * 8 + tig * 2;
            float b0 = __ldg(bias + col), b1 = __ldg(bias + col + 1);
            float2 v0 = { c[mf][nf][0] + b0, c[mf][nf][1] + b1 };
            float2 v1 = { c[mf][nf][2] + b0, c[mf][nf][3] + b1 };
            *(float2*)(C + (size_t)r0 * GG + col) = v0;
            *(float2*)(C + (size_t)(r0 + 8) * GG + col) = v1;
        }
    }
}

// --------- Persistent GRU: software-pipelined tail overlap ---------
// Iteration t: owners (warps 0-1) run tail(t-1) at the top, overlapped with
// non-owners (warps 2-7) waiting on the PEERS' deliveries + doing remote
// phases. bar2 (arrive 64 / sync 192) publishes the local h block; bar3
// syncs warp0<->warp1. One __syncthreads per iteration (red ordering).
#define GRU_TAIL(tp) { \
        const int cg = tid >> 1, half = tid & 1; \
        u64 s0 = addf2(addf2(addf2(red[cg      ], red[ 32 + cg]), \
                             addf2(red[ 64 + cg], red[ 96 + cg])), \
                       addf2(addf2(red[128 + cg], red[160 + cg]), \
                             addf2(red[192 + cg], red[224 + cg]))); \
        u64 s1 = addf2(addf2(addf2(red[256 + cg], red[288 + cg]), \
                             addf2(red[320 + cg], red[352 + cg])), \
                       addf2(addf2(red[384 + cg], red[416 + cg]), \
                             addf2(red[448 + cg], red[480 + cg]))); \
        u64 s2 = addf2(addf2(addf2(red[512 + cg], red[544 + cg]), \
                             addf2(red[576 + cg], red[608 + cg])), \
                       addf2(addf2(red[640 + cg], red[672 + cg]), \
                             addf2(red[704 + cg], red[736 + cg]))); \
        float lo0, hi0, lo1, hi1, lo2, hi2; \
        unpack2(s0, lo0, hi0); unpack2(s1, lo1, hi1); unpack2(s2, lo2, hi2); \
        float gz = (half ? hi0 : lo0) + brs[tid]       + xz; \
        float gr = (half ? hi1 : lo1) + brs[64 + tid]  + xr_; \
        float gh = (half ? hi2 : lo2) + brs[128 + tid]; \
        float er = __expf(-gr); \
        float ez = __expf(-gz); \
        float r  = __fdividef(1.f, 1.f + er); \
        float z  = __fdividef(1.f, 1.f + ez); \
        float u  = xh + r * gh; \
        float th = __fdividef(2.f, 1.f + __expf(-2.f * u)) - 1.f; \
        float hn = z * hprev + (1.f - z) * th; \
        hprev = hn; \
        if ((tp) < TT - 1) { \
            hsm[(((tp) + 1) & 1) * 256 + jbase + tid] = hn; \
            uint32_t hb = __float_as_uint(hn); \
            ST_ASYNC_F32(rem_h[((tp) + 1) & 1][0], hb, rem_bar[(tp) & 1][0]); \
            ST_ASYNC_F32(rem_h[((tp) + 1) & 1][1], hb, rem_bar[(tp) & 1][1]); \
            ST_ASYNC_F32(rem_h[((tp) + 1) & 1][2], hb, rem_bar[(tp) & 1][2]); \
        } \
        if (write_seq) { \
            size_t idx = (size_t)batch * TT * HH + (size_t)(tp) * HH + jbase + tid; \
            __nv_bfloat16 bh = __float2bfloat16(hn); \
            h1h[idx] = bh; \
            h1l[idx] = __float2bfloat16(hn - __bfloat162float(bh)); \
        } else if ((tp) == TT - 1) { \
            hfinal[batch * HH + jbase + tid] = hn; \
        } }

__global__ void __launch_bounds__(256, 1) __cluster_dims__(4, 1, 1)
gru_kernel(const float* __restrict__ xb, const float* __restrict__ rk,
           const float* __restrict__ brec, __nv_bfloat16* __restrict__ h1h,
           __nv_bfloat16* __restrict__ h1l, float* __restrict__ hfinal, int write_seq)
{
    __shared__ __align__(16) float hsm[512];          // 2 x 256 h double-buffer
    __shared__ __align__(16) u64 red[768];            // [gate][warp][cg] = 3*8*32
    __shared__ float brs[192];                        // [3][64]
    __shared__ __align__(8) u64 mbars[2];             // step-parity tx barriers

    const int tid   = threadIdx.x;
    const int rank  = blockIdx.x & 3;
    const int batch = blockIdx.x >> 2;
    const int jbase = rank * 64;
    const int w     = tid >> 5;
    const int l     = tid & 31;
    const bool own  = (tid < 64);

    int blk[4];
    #pragma unroll
    for (int p = 0; p < 4; ++p) blk[p] = ((rank + p) & 3) * 64;

    u64 w2[32][3];
    #pragma unroll
    for (int p = 0; p < 4; ++p)
        #pragma unroll
        for (int kk = 0; kk < 8; ++kk) {
            const float* wp = rk + (size_t)(blk[p] + w * 8 + kk) * GG + jbase + 2 * l;
            #pragma unroll
            for (int g = 0; g < 3; ++g) {
                float2 v = *(const float2*)(wp + g * 256);
                w2[p * 8 + kk][g] = pack2(v.x, v.y);
            }
        }

    if (tid < 192) brs[tid] = brec[(tid >> 6) * 256 + jbase + (tid & 63)];
    hsm[tid] = 0.f; hsm[256 + tid] = 0.f;

    uint32_t mb[2] = { smem_u32(&mbars[0]), smem_u32(&mbars[1]) };
    if (tid == 0) { MBAR_INIT(mb[0], 1); MBAR_INIT(mb[1], 1); }

    uint32_t rem_h[2][3], rem_bar[2][3];
    if (own) {
        #pragma unroll
        for (int b = 0; b < 2; ++b) {
            uint32_t lh = smem_u32(hsm + b * 256 + jbase + tid);
            uint32_t lb = mb[b];
            #pragma unroll
            for (int p = 0; p < 3; ++p) {
                uint32_t tr = (uint32_t)((rank + 1 + p) & 3), rh, rb;
                asm("mapa.shared::cluster.u32 %0, %1, %2;" : "=r"(rh) : "r"(lh), "r"(tr));
                asm("mapa.shared::cluster.u32 %0, %1, %2;" : "=r"(rb) : "r"(lb), "r"(tr));
                rem_h[b][p] = rh; rem_bar[b][p] = rb;
            }
        }
    }
    __syncthreads();
    asm volatile("barrier.cluster.arrive.aligned;" ::: "memory");
    asm volatile("barrier.cluster.wait.aligned;" ::: "memory");
    if (tid == 0) { MBAR_EXPECT_TX(mb[0], 768); MBAR_EXPECT_TX(mb[1], 768); }

    const float* xrow = xb + (size_t)batch * TT * GG;
    float hprev = 0.f;
    float xz = 0.f, xr_ = 0.f, xh = 0.f;   // holds x(t-1) at iteration t

#define MV_PHASE(p) { \
        float4 h4a = *(const float4*)(cur + blk[p] + w * 8); \
        float4 h4b = *(const float4*)(cur + blk[p] + w * 8 + 4); \
        float hv[8] = {h4a.x, h4a.y, h4a.z, h4a.w, h4b.x, h4b.y, h4b.z, h4b.w}; \
        _Pragma("unroll") \
        for (int kk = 0; kk < 8; ++kk) { \
            u64 hp = pack2(hv[kk], hv[kk]); \
            a2[0] = ffma2(hp, w2[(p) * 8 + kk][0], a2[0]); \
            a2[1] = ffma2(hp, w2[(p) * 8 + kk][1], a2[1]); \
            a2[2] = ffma2(hp, w2[(p) * 8 + kk][2], a2[2]); \
        } }

    for (int t = 0; t < TT; ++t) {
        const float* cur = hsm + ((t & 1) << 8);
        const int tp = t - 1;

        // prefetch x(t) (consumed by tail at iteration t+1)
        float xzn = 0.f, xrn = 0.f, xhn = 0.f;
        if (own) {
            const float* xp = xrow + (size_t)t * GG + jbase + tid;
            xzn = __ldg(xp); xrn = __ldg(xp + 256); xhn = __ldg(xp + 512);
        }

        u64 a2[3] = {0ull, 0ull, 0ull};
        if (own) {
            if (t > 0) {
                GRU_TAIL(tp)              // writes h(t-1) into cur local block
                BAR_ARRIVE(2, 256);       // publish local h to non-owners
                BAR_SYNC(3, 64);          // warp0<->warp1 h visibility
            }
            MV_PHASE(0)
            if (t > 0) {
                MBAR_WAIT_PARITY(mb[tp & 1], (tp >> 1) & 1);
                if (tid == 0 && t <= TT - 3) MBAR_EXPECT_TX(mb[(t + 1) & 1], 768);
            }
            MV_PHASE(1)
            MV_PHASE(2)
            MV_PHASE(3)
        } else {
            if (t > 0) MBAR_WAIT_PARITY(mb[tp & 1], (tp >> 1) & 1);
            MV_PHASE(1)
            MV_PHASE(2)
            MV_PHASE(3)
            if (t > 0) BAR_SYNC(2, 256);  // wait for owners' local h
            MV_PHASE(0)
        }

        red[0 * 256 + w * 32 + l] = a2[0];
        red[1 * 256 + w * 32 + l] = a2[1];
        red[2 * 256 + w * 32 + l] = a2[2];
        xz = xzn; xr_ = xrn; xh = xhn;
        __syncthreads();                   // red(t) complete before tail(t)
    }
    // epilogue: final tail for t = TT-1 (no pushes, no barriers needed)
    if (own) {
        GRU_TAIL(TT - 1)
    }
#undef MV_PHASE
}

// ---------------- Dense: out[32,64] = h2 @ wd + bd ----------------
__global__ void __launch_bounds__(256) dense_kernel(const float* __restrict__ h2,
        const float* __restrict__ wd, const float* __restrict__ bd,
        float* __restrict__ out)
{
    int o = blockIdx.x * 256 + threadIdx.x;
    int b = o >> 6, j = o & 63;
    float s = bd[j];
    for (int k = 0; k < HH; ++k) s += h2[b * HH + k] * wd[k * 64 + j];
    out[o] = s;
}

extern "C" void kernel_launch(void* const* d_in, const int* in_sizes, int n_in,
                              void* d_out, int out_size) {
    const float* x     = (const float*)d_in[0];
    const float* gamma = (const float*)d_in[1];
    const float* beta  = (const float*)d_in[2];
    const float* k1    = (const float*)d_in[3];
    const float* rk1   = (const float*)d_in[4];
    const float* b1    = (const float*)d_in[5];
    const float* k2    = (const float*)d_in[6];
    const float* rk2   = (const float*)d_in[7];
    const float* b2    = (const float*)d_in[8];
    const float* wd    = (const float*)d_in[9];
    const float* bd    = (const float*)d_in[10];
    float* out = (float*)d_out;

    float *xbuf, *h2;
    __nv_bfloat16 *xnh, *xnl, *h1h, *h1l, *wh, *wl;
    cudaGetSymbolAddress((void**)&xbuf, g_xb);
    cudaGetSymbolAddress((void**)&xnh,  g_xnh);
    cudaGetSymbolAddress((void**)&xnl,  g_xnl);
    cudaGetSymbolAddress((void**)&h1h,  g_h1h);
    cudaGetSymbolAddress((void**)&h1l,  g_h1l);
    cudaGetSymbolAddress((void**)&wh,   g_wh);
    cudaGetSymbolAddress((void**)&wl,   g_wl);
    cudaGetSymbolAddress((void**)&h2,   g_h2);

    ln_kernel<<<MTOT / 8, 256>>>(x, gamma, beta, xnh, xnl);
    wconv_kernel<<<(64 * GG + 255) / 256, 256>>>(k1, wh, wl, 64);
    gemm_mma<<<dim3(6, MTOT / 128), 256>>>(xnh, xnl, wh, wl, b1, xbuf, 64);
    gru_kernel<<<128, 256>>>(xbuf, rk1, b1 + GG, h1h, h1l, h2, 1);
    wconv_kernel<<<(256 * GG + 255) / 256, 256>>>(k2, wh, wl, 256);
    gemm_mma<<<dim3(6, MTOT / 128), 256>>>(h1h, h1l, wh, wl, b2, xbuf, 256);
    gru_kernel<<<128, 256>>>(xbuf, rk2, b2 + GG, h1h, h1l, h2, 0);
    dense_kernel<<<(BB * 64) / 256, 256>>>(h2, wd, bd, out);
}

// round 17
// speedup vs baseline: 1.1818x; 1.1818x over previous
#include <cuda_runtime.h>
#include <cuda_bf16.h>
#include <cstdint>
#include <math.h>

#define BB 32
#define TT 2048
#define FF 64
#define HH 256
#define GG 768
#define MTOT (BB*TT)

typedef unsigned long long u64;

// scratch (static device arrays: the sanctioned no-alloc workaround)
__device__ float g_xb[(size_t)MTOT*GG];                 // projection buffer (fp32)
__device__ __nv_bfloat16 g_xnh[(size_t)MTOT*FF];        // LN out hi
__device__ __nv_bfloat16 g_xnl[(size_t)MTOT*FF];        // LN out lo
__device__ __nv_bfloat16 g_h1h[(size_t)MTOT*HH];        // GRU1 seq hi
__device__ __nv_bfloat16 g_h1l[(size_t)MTOT*HH];        // GRU1 seq lo
__device__ __nv_bfloat16 g_wh[GG*HH];                   // packed W [N][K] hi
__device__ __nv_bfloat16 g_wl[GG*HH];                   // packed W [N][K] lo
__device__ float g_h2[BB*HH];

__device__ __forceinline__ u64 ffma2(u64 a, u64 b, u64 c) {
    u64 d;
    asm("fma.rn.f32x2 %0, %1, %2, %3;" : "=l"(d) : "l"(a), "l"(b), "l"(c));
    return d;
}
__device__ __forceinline__ u64 addf2(u64 a, u64 b) {
    u64 d;
    asm("add.rn.f32x2 %0, %1, %2;" : "=l"(d) : "l"(a), "l"(b));
    return d;
}
__device__ __forceinline__ u64 pack2(float x, float y) {
    u64 d;
    asm("mov.b64 %0, {%1, %2};" : "=l"(d) : "f"(x), "f"(y));
    return d;
}
__device__ __forceinline__ void unpack2(u64 v, float& lo, float& hi) {
    asm("mov.b64 {%0, %1}, %2;" : "=f"(lo), "=f"(hi) : "l"(v));
}
__device__ __forceinline__ uint32_t smem_u32(const void* p) {
    return (uint32_t)__cvta_generic_to_shared(p);
}

#define MBAR_INIT(addr, cnt) \
    asm volatile("mbarrier.init.shared.b64 [%0], %1;" :: "r"(addr), "r"(cnt) : "memory")
#define MBAR_EXPECT_TX(addr, bytes) \
    asm volatile("mbarrier.arrive.expect_tx.shared.b64 _, [%0], %1;" :: "r"(addr), "r"(bytes) : "memory")
#define MBAR_WAIT_PARITY(addr, par) do { \
    uint32_t _done = 0; \
    while (!_done) { \
        asm volatile("{\n\t.reg .pred P;\n\t" \
            "mbarrier.try_wait.parity.acquire.cta.shared::cta.b64 P, [%1], %2, 0x989680;\n\t" \
            "selp.b32 %0, 1, 0, P;\n\t}" \
            : "=r"(_done) : "r"(addr), "r"(par) : "memory"); \
    } } while (0)
#define ST_ASYNC_F32(raddr, val, rbar) \
    asm volatile("st.async.shared::cluster.mbarrier::complete_tx::bytes.b32 [%0], %1, [%2];" \
        :: "r"(raddr), "r"(val), "r"(rbar) : "memory")
#define CP_ASYNC16(dst, src) \
    asm volatile("cp.async.cg.shared.global [%0], [%1], 16;" :: "r"(dst), "l"(src) : "memory")
#define CP_COMMIT() asm volatile("cp.async.commit_group;" ::: "memory")
#define CP_WAIT(n)  asm volatile("cp.async.wait_group %0;" :: "n"(n) : "memory")

// mma.sync bf16: D(f32) += A(bf16) * B(bf16). m16n8k16, row.col.
#define MMA_BF16(c, a, b) \
    asm volatile("mma.sync.aligned.m16n8k16.row.col.f32.bf16.bf16.f32 " \
        "{%0,%1,%2,%3}, {%4,%5,%6,%7}, {%8,%9}, {%0,%1,%2,%3};" \
        : "+f"((c)[0]), "+f"((c)[1]), "+f"((c)[2]), "+f"((c)[3]) \
        : "r"((a)[0]), "r"((a)[1]), "r"((a)[2]), "r"((a)[3]), \
          "r"((b)[0]), "r"((b)[1]))

// ---------------- LayerNorm -> bf16 hi/lo split ----------------
__global__ void __launch_bounds__(256) ln_kernel(const float* __restrict__ x,
        const float* __restrict__ gamma, const float* __restrict__ beta,
        __nv_bfloat16* __restrict__ xnh, __nv_bfloat16* __restrict__ xnl)
{
    int row  = blockIdx.x * 8 + (threadIdx.x >> 5);
    int lane = threadIdx.x & 31;
    const float* xr = x + (size_t)row * FF;
    float v0 = xr[lane], v1 = xr[lane + 32];
    float s = v0 + v1;
    #pragma unroll
    for (int o = 16; o > 0; o >>= 1) s += __shfl_xor_sync(0xffffffffu, s, o);
    float mu = s * (1.f / FF);
    float d0 = v0 - mu, d1 = v1 - mu;
    float q = d0 * d0 + d1 * d1;
    #pragma unroll
    for (int o = 16; o > 0; o >>= 1) q += __shfl_xor_sync(0xffffffffu, q, o);
    float inv = rsqrtf(q * (1.f / FF) + 1e-3f);
    float o0 = d0 * inv * gamma[lane]      + beta[lane];
    float o1 = d1 * inv * gamma[lane + 32] + beta[lane + 32];
    size_t i0 = (size_t)row * FF + lane;
    __nv_bfloat16 h0 = __float2bfloat16(o0);
    __nv_bfloat16 h1 = __float2bfloat16(o1);
    xnh[i0] = h0;      xnl[i0]      = __float2bfloat16(o0 - __bfloat162float(h0));
    xnh[i0 + 32] = h1; xnl[i0 + 32] = __float2bfloat16(o1 - __bfloat162float(h1));
}

// ---- pack weights: W[K][N] fp32 -> [N][K] bf16 hi/lo ----
__global__ void wconv_kernel(const float* __restrict__ Wm,
        __nv_bfloat16* __restrict__ Wh, __nv_bfloat16* __restrict__ Wl, int K)
{
    int idx = blockIdx.x * 256 + threadIdx.x;
    if (idx >= K * GG) return;
    int n = idx / K, k = idx - n * K;
    float v = Wm[(size_t)k * GG + n];
    __nv_bfloat16 h = __float2bfloat16(v);
    Wh[idx] = h;
    Wl[idx] = __float2bfloat16(v - __bfloat162float(h));
}

// ---- mma.sync bf16 GEMM, cp.async 2-stage pipeline ----
// Layout per stage (dynamic smem): 4 buffers (Ah,Al,Bh,Bl), each 128 rows x
// 40 bf16 (80B row stride); stage stride 40960B, total 81920B.
#define GSM_BUF 10240
#define GSM_STAGE 40960
__global__ void __launch_bounds__(256) gemm_mma(
        const __nv_bfloat16* __restrict__ Ah, const __nv_bfloat16* __restrict__ Al,
        const __nv_bfloat16* __restrict__ Bh, const __nv_bfloat16* __restrict__ Bl,
        const float* __restrict__ bias, float* __restrict__ C, int K)
{
    extern __shared__ char gsm[];
    const uint32_t gsm_b = smem_u32(gsm);
    const int tid = threadIdx.x, wid = tid >> 5, lane = tid & 31;
    const int bm = blockIdx.y * 128, bn = blockIdx.x * 128;
    const int wm = wid & 1, wn = wid >> 1;
    const int g = lane >> 2, tig = lane & 3;
    const int nch = K >> 5;

    float c[4][4][4];
    #pragma unroll
    for (int i = 0; i < 4; ++i)
        #pragma unroll
        for (int j = 0; j < 4; ++j)
            #pragma unroll
            for (int r = 0; r < 4; ++r) c[i][j][r] = 0.f;

#define GLOAD(st, ch) { \
        int k0 = (ch) * 32; \
        _Pragma("unroll") \
        for (int i = tid; i < 512; i += 256) { \
            int row = i >> 2, seg = i & 3; \
            uint32_t d = gsm_b + (st) * GSM_STAGE + row * 80 + seg * 16; \
            size_t offA = (size_t)(bm + row) * K + k0 + seg * 8; \
            size_t offB = (size_t)(bn + row) * K + k0 + seg * 8; \
            CP_ASYNC16(d,                Ah + offA); \
            CP_ASYNC16(d + GSM_BUF,      Al + offA); \
            CP_ASYNC16(d + 2 * GSM_BUF,  Bh + offB); \
            CP_ASYNC16(d + 3 * GSM_BUF,  Bl + offB); \
        } }

    GLOAD(0, 0)
    CP_COMMIT();

    for (int ch = 0; ch < nch; ++ch) {
        const int st = ch & 1;
        if (ch + 1 < nch) {
            GLOAD(st ^ 1, ch + 1)
            CP_COMMIT();
            CP_WAIT(1);
        } else {
            CP_WAIT(0);
        }
        __syncthreads();
        const __nv_bfloat16* sAh = (const __nv_bfloat16*)(gsm + st * GSM_STAGE);
        const __nv_bfloat16* sAl = (const __nv_bfloat16*)(gsm + st * GSM_STAGE + GSM_BUF);
        const __nv_bfloat16* sBh = (const __nv_bfloat16*)(gsm + st * GSM_STAGE + 2 * GSM_BUF);
        const __nv_bfloat16* sBl = (const __nv_bfloat16*)(gsm + st * GSM_STAGE + 3 * GSM_BUF);
        #pragma unroll
        for (int kf = 0; kf < 2; ++kf) {
            const int kc = kf * 16 + tig * 2;
            uint32_t aH[4][4], aL[4][4], bH[4][2], bL[4][2];
            #pragma unroll
            for (int mf = 0; mf < 4; ++mf) {
                int r = wm * 64 + mf * 16 + g;
                aH[mf][0] = *(const uint32_t*)(sAh + r * 40 + kc);
                aH[mf][1] = *(const uint32_t*)(sAh + (r + 8) * 40 + kc);
                aH[mf][2] = *(const uint32_t*)(sAh + r * 40 + kc + 8);
                aH[mf][3] = *(const uint32_t*)(sAh + (r + 8) * 40 + kc + 8);
                aL[mf][0] = *(const uint32_t*)(sAl + r * 40 + kc);
                aL[mf][1] = *(const uint32_t*)(sAl + (r + 8) * 40 + kc);
                aL[mf][2] = *(const uint32_t*)(sAl + r * 40 + kc + 8);
                aL[mf][3] = *(const uint32_t*)(sAl + (r + 8) * 40 + kc + 8);
            }
            #pragma unroll
            for (int nf = 0; nf < 4; ++nf) {
                int n = wn * 32 + nf * 8 + g;
                bH[nf][0] = *(const uint32_t*)(sBh + n * 40 + kc);
                bH[nf][1] = *(const uint32_t*)(sBh + n * 40 + kc + 8);
                bL[nf][0] = *(const uint32_t*)(sBl + n * 40 + kc);
                bL[nf][1] = *(const uint32_t*)(sBl + n * 40 + kc + 8);
            }
            #pragma unroll
            for (int mf = 0; mf < 4; ++mf)
                #pragma unroll
                for (int nf = 0; nf < 4; ++nf) {
                    MMA_BF16(c[mf][nf], aH[mf], bH[nf]);
                    MMA_BF16(c[mf][nf], aH[mf], bL[nf]);
                    MMA_BF16(c[mf][nf], aL[mf], bH[nf]);
                }
        }
        __syncthreads();
    }
    #pragma unroll
    for (int mf = 0; mf < 4; ++mf) {
        int r0 = bm + wm * 64 + mf * 16 + g;
        #pragma unroll
        for (int nf = 0; nf < 4; ++nf) {
            int col = bn + wn * 32 + nf * 8 + tig * 2;
            float b0 = __ldg(bias + col), b1 = __ldg(bias + col + 1);
            float2 v0 = { c[mf][nf][0] + b0, c[mf][nf][1] + b1 };
            float2 v1 = { c[mf][nf][2] + b0, c[mf][nf][3] + b1 };
            *(float2*)(C + (size_t)r0 * GG + col) = v0;
            *(float2*)(C + (size_t)(r0 + 8) * GG + col) = v1;
        }
    }
#undef GLOAD
}

// --------- Persistent GRU: EXACT R15 structure (best: 2901us) ---------
__global__ void __launch_bounds__(256, 1) __cluster_dims__(4, 1, 1)
gru_kernel(const float* __restrict__ xb, const float* __restrict__ rk,
           const float* __restrict__ brec, __nv_bfloat16* __restrict__ h1h,
           __nv_bfloat16* __restrict__ h1l, float* __restrict__ hfinal, int write_seq)
{
    __shared__ __align__(16) float hsm[512];          // 2 x 256 h double-buffer
    __shared__ __align__(16) u64 red[768];            // [gate][warp][cg] = 3*8*32
    __shared__ float brs[192];                        // [3][64]
    __shared__ __align__(8) u64 mbars[2];             // step-parity tx barriers

    const int tid   = threadIdx.x;
    const int rank  = blockIdx.x & 3;
    const int batch = blockIdx.x >> 2;
    const int jbase = rank * 64;
    const int w     = tid >> 5;
    const int l     = tid & 31;

    int blk[4];
    #pragma unroll
    for (int p = 0; p < 4; ++p) blk[p] = ((rank + p) & 3) * 64;

    u64 w2[32][3];
    #pragma unroll
    for (int p = 0; p < 4; ++p)
        #pragma unroll
        for (int kk = 0; kk < 8; ++kk) {
            const float* wp = rk + (size_t)(blk[p] + w * 8 + kk) * GG + jbase + 2 * l;
            #pragma unroll
            for (int g = 0; g < 3; ++g) {
                float2 v = *(const float2*)(wp + g * 256);
                w2[p * 8 + kk][g] = pack2(v.x, v.y);
            }
        }

    if (tid < 192) brs[tid] = brec[(tid >> 6) * 256 + jbase + (tid & 63)];
    hsm[tid] = 0.f; hsm[256 + tid] = 0.f;

    uint32_t mb[2] = { smem_u32(&mbars[0]), smem_u32(&mbars[1]) };
    if (tid == 0) { MBAR_INIT(mb[0], 1); MBAR_INIT(mb[1], 1); }

    uint32_t rem_h[2][3], rem_bar[2][3];
    if (tid < 64) {
        #pragma unroll
        for (int b = 0; b < 2; ++b) {
            uint32_t lh = smem_u32(hsm + b * 256 + jbase + tid);
            uint32_t lb = mb[b];
            #pragma unroll
            for (int p = 0; p < 3; ++p) {
                uint32_t tr = (uint32_t)((rank + 1 + p) & 3), rh, rb;
                asm("mapa.shared::cluster.u32 %0, %1, %2;" : "=r"(rh) : "r"(lh), "r"(tr));
                asm("mapa.shared::cluster.u32 %0, %1, %2;" : "=r"(rb) : "r"(lb), "r"(tr));
                rem_h[b][p] = rh; rem_bar[b][p] = rb;
            }
        }
    }
    __syncthreads();
    asm volatile("barrier.cluster.arrive.aligned;" ::: "memory");
    asm volatile("barrier.cluster.wait.aligned;" ::: "memory");
    if (tid == 0) { MBAR_EXPECT_TX(mb[0], 768); MBAR_EXPECT_TX(mb[1], 768); }

    const float* xrow = xb + (size_t)batch * TT * GG;
    float hprev = 0.f;

    float xz = 0.f, xr_ = 0.f, xh = 0.f;
    if (tid < 64) {
        const float* xp = xrow + jbase + tid;
        xz = __ldg(xp); xr_ = __ldg(xp + 256); xh = __ldg(xp + 512);
    }

#define MV_PHASE(p) { \
        float4 h4a = *(const float4*)(cur + blk[p] + w * 8); \
        float4 h4b = *(const float4*)(cur + blk[p] + w * 8 + 4); \
        float hv[8] = {h4a.x, h4a.y, h4a.z, h4a.w, h4b.x, h4b.y, h4b.z, h4b.w}; \
        _Pragma("unroll") \
        for (int kk = 0; kk < 8; ++kk) { \
            u64 hp = pack2(hv[kk], hv[kk]); \
            a2[0] = ffma2(hp, w2[(p) * 8 + kk][0], a2[0]); \
            a2[1] = ffma2(hp, w2[(p) * 8 + kk][1], a2[1]); \
            a2[2] = ffma2(hp, w2[(p) * 8 + kk][2], a2[2]); \
        } }

    for (int t = 0; t < TT; ++t) {
        const float* cur = hsm + ((t & 1) << 8);
        float*       nxt = hsm + (((t & 1) ^ 1) << 8);
        const int    nb  = (t & 1) ^ 1;

        float xzn = 0.f, xrn = 0.f, xhn = 0.f;
        if (tid < 64 && t < TT - 1) {
            const float* xp = xrow + (size_t)(t + 1) * GG + jbase + tid;
            xzn = __ldg(xp); xrn = __ldg(xp + 256); xhn = __ldg(xp + 512);
        }

        u64 a2[3] = {0ull, 0ull, 0ull};
        MV_PHASE(0)
        if (t > 0) {
            MBAR_WAIT_PARITY(mb[(t - 1) & 1], ((t - 1) >> 1) & 1);
            if (tid == 0 && t <= TT - 3) MBAR_EXPECT_TX(mb[(t + 1) & 1], 768);
        }
        MV_PHASE(1)
        MV_PHASE(2)
        MV_PHASE(3)

        red[0 * 256 + w * 32 + l] = a2[0];
        red[1 * 256 + w * 32 + l] = a2[1];
        red[2 * 256 + w * 32 + l] = a2[2];
        __syncthreads();

        if (tid < 64) {
            const int cg = tid >> 1, half = tid & 1;
            u64 s0 = addf2(addf2(addf2(red[cg      ], red[ 32 + cg]),
                                 addf2(red[ 64 + cg], red[ 96 + cg])),
                           addf2(addf2(red[128 + cg], red[160 + cg]),
                                 addf2(red[192 + cg], red[224 + cg])));
            u64 s1 = addf2(addf2(addf2(red[256 + cg], red[288 + cg]),
                                 addf2(red[320 + cg], red[352 + cg])),
                           addf2(addf2(red[384 + cg], red[416 + cg]),
                                 addf2(red[448 + cg], red[480 + cg])));
            u64 s2 = addf2(addf2(addf2(red[512 + cg], red[544 + cg]),
                                 addf2(red[576 + cg], red[608 + cg])),
                           addf2(addf2(red[640 + cg], red[672 + cg]),
                                 addf2(red[704 + cg], red[736 + cg])));
            float lo0, hi0, lo1, hi1, lo2, hi2;
            unpack2(s0, lo0, hi0); unpack2(s1, lo1, hi1); unpack2(s2, lo2, hi2);
            float gz = (half ? hi0 : lo0) + brs[tid]       + xz;
            float gr = (half ? hi1 : lo1) + brs[64 + tid]  + xr_;
            float gh = (half ? hi2 : lo2) + brs[128 + tid];
            float er = __expf(-gr);
            float ez = __expf(-gz);
            float r  = __fdividef(1.f, 1.f + er);
            float z  = __fdividef(1.f, 1.f + ez);
            float u  = xh + r * gh;
            float th = __fdividef(2.f, 1.f + __expf(-2.f * u)) - 1.f;
            float hn = z * hprev + (1.f - z) * th;
            hprev = hn;
            nxt[jbase + tid] = hn;
            if (t < TT - 1) {
                uint32_t hb = __float_as_uint(hn);
                ST_ASYNC_F32(rem_h[nb][0], hb, rem_bar[t & 1][0]);
                ST_ASYNC_F32(rem_h[nb][1], hb, rem_bar[t & 1][1]);
                ST_ASYNC_F32(rem_h[nb][2], hb, rem_bar[t & 1][2]);
            }
            if (write_seq) {
                size_t idx = (size_t)batch * TT * HH + (size_t)t * HH + jbase + tid;
                __nv_bfloat16 bh = __float2bfloat16(hn);
                h1h[idx] = bh;
                h1l[idx] = __float2bfloat16(hn - __bfloat162float(bh));
            } else if (t == TT - 1) {
                hfinal[batch * HH + jbase + tid] = hn;
            }
        }
        xz = xzn; xr_ = xrn; xh = xhn;
        __syncthreads();
    }
#undef MV_PHASE
}

// ---------------- Dense: out[32,64] = h2 @ wd + bd ----------------
__global__ void __launch_bounds__(256) dense_kernel(const float* __restrict__ h2,
        const float* __restrict__ wd, const float* __restrict__ bd,
        float* __restrict__ out)
{
    int o = blockIdx.x * 256 + threadIdx.x;
    int b = o >> 6, j = o & 63;
    float s = bd[j];
    for (int k = 0; k < HH; ++k) s += h2[b * HH + k] * wd[k * 64 + j];
    out[o] = s;
}

extern "C" void kernel_launch(void* const* d_in, const int* in_sizes, int n_in,
                              void* d_out, int out_size) {
    const float* x     = (const float*)d_in[0];
    const float* gamma = (const float*)d_in[1];
    const float* beta  = (const float*)d_in[2];
    const float* k1    = (const float*)d_in[3];
    const float* rk1   = (const float*)d_in[4];
    const float* b1    = (const float*)d_in[5];
    const float* k2    = (const float*)d_in[6];
    const float* rk2   = (const float*)d_in[7];
    const float* b2    = (const float*)d_in[8];
    const float* wd    = (const float*)d_in[9];
    const float* bd    = (const float*)d_in[10];
    float* out = (float*)d_out;

    float *xbuf, *h2;
    __nv_bfloat16 *xnh, *xnl, *h1h, *h1l, *wh, *wl;
    cudaGetSymbolAddress((void**)&xbuf, g_xb);
    cudaGetSymbolAddress((void**)&xnh,  g_xnh);
    cudaGetSymbolAddress((void**)&xnl,  g_xnl);
    cudaGetSymbolAddress((void**)&h1h,  g_h1h);
    cudaGetSymbolAddress((void**)&h1l,  g_h1l);
    cudaGetSymbolAddress((void**)&wh,   g_wh);
    cudaGetSymbolAddress((void**)&wl,   g_wl);
    cudaGetSymbolAddress((void**)&h2,   g_h2);

    cudaFuncSetAttribute(gemm_mma, cudaFuncAttributeMaxDynamicSharedMemorySize, 2 * GSM_STAGE);

    ln_kernel<<<MTOT / 8, 256>>>(x, gamma, beta, xnh, xnl);
    wconv_kernel<<<(64 * GG + 255) / 256, 256>>>(k1, wh, wl, 64);
    gemm_mma<<<dim3(6, MTOT / 128), 256, 2 * GSM_STAGE>>>(xnh, xnl, wh, wl, b1, xbuf, 64);
    gru_kernel<<<128, 256>>>(xbuf, rk1, b1 + GG, h1h, h1l, h2, 1);
    wconv_kernel<<<(256 * GG + 255) / 256, 256>>>(k2, wh, wl, 256);
    gemm_mma<<<dim3(6, MTOT / 128), 256, 2 * GSM_STAGE>>>(h1h, h1l, wh, wl, b2, xbuf, 256);
    gru_kernel<<<128, 256>>>(xbuf, rk2, b2 + GG, h1h, h1l, h2, 0);
    dense_kernel<<<(BB * 64) / 256, 256>>>(h2, wd, bd, out);
}